// round 7
// baseline (speedup 1.0000x reference)
#include <cuda_runtime.h>
#include <math.h>

// Problem constants (fixed by reference)
#define IMG_W 128
#define IMG_H 128
#define TILE_W 8
#define TILE_H 8
#define PIX   64              // pixels per tile
#define SPLIT 4               // gaussian-axis interleave in render
#define NT    (PIX * SPLIT)   // 256 threads per render block
#define MAXN  4096            // max gaussians per batch (fits u16 indices)
#define MAXB  8
#define SLICE 128             // gaussians per prep block
#define MAXSLICES (MAXN / SLICE)   // 32

// Per-batch, per-slice compacted survivor params (image-level cull applied).
// Slice s of batch b occupies [b*MAXN + s*SLICE, +g_cntS[b*MAXSLICES+s]).
// g_c1 = {proj_x, proj_y, K2 = -1/(2*var*ln2), log2(opacity)}
// g_c2 = {color_r, color_g, color_b, 0}
static __device__ float4 g_c1[MAXB * MAXN];
static __device__ float4 g_c2[MAXB * MAXN];
static __device__ int    g_cntS[MAXB * MAXSLICES];

// grid = (numSlices, B), block = SLICE threads, one gaussian per thread.
// Params + image-rect cull + ballot compaction within the slice (deterministic).
__global__ void __launch_bounds__(SLICE)
prep_kernel(const float* __restrict__ pos,
            const float* __restrict__ col,
            const float* __restrict__ opa,
            const float* __restrict__ sca,
            const float* __restrict__ qv,
            const float* __restrict__ tv,
            int N) {
    __shared__ int sWarp[SLICE / 32];

    const int s    = blockIdx.x;
    const int b    = blockIdx.y;
    const int t    = threadIdx.x;
    const int lane = t & 31;
    const int wid  = t >> 5;
    const int g    = s * SLICE + t;

    // Quaternion -> rotation (normalized), matching reference exactly.
    float qw = qv[b * 4 + 0], qx = qv[b * 4 + 1], qy = qv[b * 4 + 2], qz = qv[b * 4 + 3];
    float inv = rsqrtf(qw * qw + qx * qx + qy * qy + qz * qz);
    qw *= inv; qx *= inv; qy *= inv; qz *= inv;
    float R00 = 1.f - 2.f * (qy * qy + qz * qz), R01 = 2.f * (qx * qy - qz * qw), R02 = 2.f * (qx * qz + qy * qw);
    float R10 = 2.f * (qx * qy + qz * qw), R11 = 1.f - 2.f * (qx * qx + qz * qz), R12 = 2.f * (qy * qz - qx * qw);
    float R20 = 2.f * (qx * qz - qy * qw), R21 = 2.f * (qy * qz + qx * qw), R22 = 1.f - 2.f * (qx * qx + qy * qy);

    bool keepIt = false;
    float4 p1;
    if (g < N) {
        float px = pos[g * 3 + 0], py = pos[g * 3 + 1], pz = pos[g * 3 + 2];
        float cxm = R00 * px + R01 * py + R02 * pz + tv[b * 3 + 0];
        float cym = R10 * px + R11 * py + R12 * pz + tv[b * 3 + 1];
        float czm = R20 * px + R21 * py + R22 * pz + tv[b * 3 + 2];
        float projx = cxm / czm * 500.0f + 64.0f;
        float projy = cym / czm * 500.0f + 64.0f;

        float sc = sca[g];
        float var = sc * sc;
        float K2 = -0.72134752044f / var;             // exp(-.5 d2/var) = 2^(K2*d2)
        float lo = log2f(fmaxf(opa[g], 1e-30f));

        // Image-level conservative cull: max weight over the whole image rect.
        float dx = fmaxf(0.f, fmaxf(0.f - projx, projx - (float)(IMG_W - 1)));
        float dy = fmaxf(0.f, fmaxf(0.f - projy, projy - (float)(IMG_H - 1)));
        float amax = fmaf(K2, fmaf(dx, dx, dy * dy), lo);
        keepIt = (amax > -60.f);    // NaN (z~0) fails -> culled
        p1 = make_float4(projx, projy, K2, lo);
    }

    // Ballot compaction within warp, then 4-warp combine (deterministic).
    unsigned m = __ballot_sync(0xffffffffu, keepIt);
    int myOff = __popc(m & ((1u << lane) - 1u));
    if (lane == 0) sWarp[wid] = __popc(m);
    __syncthreads();

    int warpBase = 0, cnt = 0;
    #pragma unroll
    for (int w = 0; w < SLICE / 32; ++w) {
        int c = sWarp[w];
        if (w < wid) warpBase += c;
        cnt += c;
    }

    if (keepIt) {
        int wpos = b * MAXN + s * SLICE + warpBase + myOff;
        g_c1[wpos] = p1;
        g_c2[wpos] = make_float4(col[g * 3 + 0], col[g * 3 + 1], col[g * 3 + 2], 0.f);
    }
    if (t == 0) g_cntS[b * MAXSLICES + s] = cnt;
}

__global__ void __launch_bounds__(NT)
render_kernel(float* __restrict__ out, int numSlices) {
    __shared__ int    sCnt[MAXSLICES];      // per-slice survivor counts
    __shared__ unsigned short sIdx[MAXN];   // tile survivors (region-layout idx)
    __shared__ int    sWarp[NT / 32];
    __shared__ float4 sAcc[NT];

    const int t    = threadIdx.x;
    const int lane = t & 31;
    const int wid  = t >> 5;                // 0..7
    const int sub  = wid >> 1;              // 0..3
    const int pt   = t & (PIX - 1);         // 0..63
    const int b    = blockIdx.z;
    const int x0   = blockIdx.x * TILE_W;
    const int y0   = blockIdx.y * TILE_H;
    const float xf = (float)(x0 + (pt & (TILE_W - 1)));
    const float yf = (float)(y0 + (pt >> 3));

    const float fx0 = (float)x0, fx1 = (float)(x0 + TILE_W - 1);
    const float fy0 = (float)y0, fy1 = (float)(y0 + TILE_H - 1);

    const float4* __restrict__ C1 = g_c1 + b * MAXN;
    const float4* __restrict__ C2 = g_c2 + b * MAXN;

    if (t < numSlices) sCnt[t] = g_cntS[b * MAXSLICES + t];
    __syncthreads();

    // ---- Phase 1: tile-bbox test over ragged compacted slices ----
    unsigned keep = 0;
    int k = 0, j = 0;
    for (int s = 0; s < numSlices; ++s) {
        int cnt = sCnt[s];
        for (int i = t; i < cnt; i += NT, ++j) {
            float4 p = C1[s * SLICE + i];
            float dx = fmaxf(0.f, fmaxf(fx0 - p.x, p.x - fx1));
            float dy = fmaxf(0.f, fmaxf(fy0 - p.y, p.y - fy1));
            float amax = fmaf(p.z, fmaf(dx, dx, dy * dy), p.w);
            if (amax > -60.f) { keep |= (1u << j); ++k; }
        }
    }

    // ---- Phase 2: warp scan + 8-warp combine ----
    int incl = k;
    #pragma unroll
    for (int o = 1; o < 32; o <<= 1) {
        int v = __shfl_up_sync(0xffffffffu, incl, o);
        if (lane >= o) incl += v;
    }
    if (lane == 31) sWarp[wid] = incl;
    __syncthreads();

    int warpBase = 0, tcnt = 0;
    #pragma unroll
    for (int w = 0; w < NT / 32; ++w) {
        int c = sWarp[w];
        if (w < wid) warpBase += c;
        tcnt += c;
    }
    int wpos = warpBase + incl - k;

    // ---- Phase 3: deterministic compaction (replay identical iteration) ----
    j = 0;
    for (int s = 0; s < numSlices; ++s) {
        int cnt = sCnt[s];
        for (int i = t; i < cnt; i += NT, ++j) {
            if (keep & (1u << j)) sIdx[wpos++] = (unsigned short)(s * SLICE + i);
        }
    }
    __syncthreads();

    // ---- Phase 4: each sub strides the survivor list by SPLIT ----
    float accR = 0.f, accG = 0.f, accB = 0.f, accD = 0.f;
    #pragma unroll 2
    for (int i = sub; i < tcnt; i += SPLIT) {
        int gi = (int)sIdx[i];
        float4 p1 = C1[gi];          // broadcast LDG.128, L1/L2-resident
        float4 p2 = C2[gi];
        float dx = xf - p1.x;
        float dy = yf - p1.y;
        float d2 = fmaf(dx, dx, dy * dy);
        float e  = exp2f(fmaf(p1.z, d2, p1.w));
        accD += e;
        accR = fmaf(e, p2.x, accR);
        accG = fmaf(e, p2.y, accG);
        accB = fmaf(e, p2.z, accB);
    }
    sAcc[t] = make_float4(accR, accG, accB, accD);
    __syncthreads();

    // ---- Phase 5: fixed-order combine of 4 sub partials, write out ----
    if (t < PIX) {
        float4 a0 = sAcc[t];
        float4 a1 = sAcc[t + PIX];
        float4 a2 = sAcc[t + 2 * PIX];
        float4 a3 = sAcc[t + 3 * PIX];
        float r  = (a0.x + a1.x) + (a2.x + a3.x);
        float g  = (a0.y + a1.y) + (a2.y + a3.y);
        float bl = (a0.z + a1.z) + (a2.z + a3.z);
        float d  = (a0.w + a1.w) + (a2.w + a3.w);
        float invd = 1.0f / (d + 1e-8f);
        int px = x0 + (t & (TILE_W - 1));
        int py = y0 + (t >> 3);
        int o = ((b * 3 + 0) * IMG_H + py) * IMG_W + px;
        out[o]                     = r  * invd;
        out[o + IMG_H * IMG_W]     = g  * invd;
        out[o + 2 * IMG_H * IMG_W] = bl * invd;
    }
}

extern "C" void kernel_launch(void* const* d_in, const int* in_sizes, int n_in,
                              void* d_out, int out_size) {
    const float* positions = (const float*)d_in[0];  // (N,3)
    const float* colors    = (const float*)d_in[1];  // (N,3)
    const float* opacities = (const float*)d_in[2];  // (N,1)
    const float* scales    = (const float*)d_in[3];  // (N,1)
    const float* qvec      = (const float*)d_in[4];  // (B,4)
    const float* tvec      = (const float*)d_in[5];  // (B,3)

    int N = in_sizes[0] / 3;
    int B = in_sizes[4] / 4;
    if (N > MAXN || B > MAXB) return;  // capacity guard (problem is N=4096, B=2)

    int numSlices = (N + SLICE - 1) / SLICE;
    dim3 pgrid(numSlices, B);
    prep_kernel<<<pgrid, SLICE>>>(positions, colors, opacities, scales, qvec, tvec, N);

    dim3 grid(IMG_W / TILE_W, IMG_H / TILE_H, B);
    render_kernel<<<grid, NT>>>((float*)d_out, numSlices);
}

// round 8
// speedup vs baseline: 1.1200x; 1.1200x over previous
#include <cuda_runtime.h>
#include <math.h>

// Problem constants (fixed by reference)
#define IMG_W 128
#define IMG_H 128
#define TILE  16              // 16x16 tiles -> 8*8*B = 128 blocks (single wave)
#define NT    256             // one thread per pixel
#define MAXN  4096            // max gaussians per batch (fits u16 indices)
#define MAXB  8
#define SLICE 128             // gaussians per prep block
#define MAXSLICES (MAXN / SLICE)   // 32

// Stage-1 output: per-batch, per-slice compacted survivors (ragged).
static __device__ float4 g_c1[MAXB * MAXN];
static __device__ float4 g_c2[MAXB * MAXN];
static __device__ int    g_cntS[MAXB * MAXSLICES];
// Stage-2 output: dense per-batch survivor list.
// g_d1 = {proj_x, proj_y, K2 = -1/(2*var*ln2), log2(opacity)}
// g_d2 = {color_r, color_g, color_b, 0}
static __device__ float4 g_d1[MAXB * MAXN];
static __device__ float4 g_d2[MAXB * MAXN];
static __device__ int    g_M[MAXB];

// grid = (numSlices, B), block = SLICE threads, one gaussian per thread.
// Params + image-rect cull + ballot compaction within the slice (deterministic).
__global__ void __launch_bounds__(SLICE)
prep_kernel(const float* __restrict__ pos,
            const float* __restrict__ col,
            const float* __restrict__ opa,
            const float* __restrict__ sca,
            const float* __restrict__ qv,
            const float* __restrict__ tv,
            int N) {
    __shared__ int sWarp[SLICE / 32];

    const int s    = blockIdx.x;
    const int b    = blockIdx.y;
    const int t    = threadIdx.x;
    const int lane = t & 31;
    const int wid  = t >> 5;
    const int g    = s * SLICE + t;

    // Quaternion -> rotation (normalized), matching reference exactly.
    float qw = qv[b * 4 + 0], qx = qv[b * 4 + 1], qy = qv[b * 4 + 2], qz = qv[b * 4 + 3];
    float inv = rsqrtf(qw * qw + qx * qx + qy * qy + qz * qz);
    qw *= inv; qx *= inv; qy *= inv; qz *= inv;
    float R00 = 1.f - 2.f * (qy * qy + qz * qz), R01 = 2.f * (qx * qy - qz * qw), R02 = 2.f * (qx * qz + qy * qw);
    float R10 = 2.f * (qx * qy + qz * qw), R11 = 1.f - 2.f * (qx * qx + qz * qz), R12 = 2.f * (qy * qz - qx * qw);
    float R20 = 2.f * (qx * qz - qy * qw), R21 = 2.f * (qy * qz + qx * qw), R22 = 1.f - 2.f * (qx * qx + qy * qy);

    bool keepIt = false;
    float4 p1;
    if (g < N) {
        float px = pos[g * 3 + 0], py = pos[g * 3 + 1], pz = pos[g * 3 + 2];
        float cxm = R00 * px + R01 * py + R02 * pz + tv[b * 3 + 0];
        float cym = R10 * px + R11 * py + R12 * pz + tv[b * 3 + 1];
        float czm = R20 * px + R21 * py + R22 * pz + tv[b * 3 + 2];
        float projx = cxm / czm * 500.0f + 64.0f;
        float projy = cym / czm * 500.0f + 64.0f;

        float sc = sca[g];
        float var = sc * sc;
        float K2 = -0.72134752044f / var;             // exp(-.5 d2/var) = 2^(K2*d2)
        float lo = log2f(fmaxf(opa[g], 1e-30f));

        // Image-level conservative cull: max weight over the whole image rect.
        float dx = fmaxf(0.f, fmaxf(0.f - projx, projx - (float)(IMG_W - 1)));
        float dy = fmaxf(0.f, fmaxf(0.f - projy, projy - (float)(IMG_H - 1)));
        float amax = fmaf(K2, fmaf(dx, dx, dy * dy), lo);
        keepIt = (amax > -60.f);    // NaN (z~0) fails -> culled
        p1 = make_float4(projx, projy, K2, lo);
    }

    // Ballot compaction within warp, then 4-warp combine (deterministic).
    unsigned m = __ballot_sync(0xffffffffu, keepIt);
    int myOff = __popc(m & ((1u << lane) - 1u));
    if (lane == 0) sWarp[wid] = __popc(m);
    __syncthreads();

    int warpBase = 0, cnt = 0;
    #pragma unroll
    for (int w = 0; w < SLICE / 32; ++w) {
        int c = sWarp[w];
        if (w < wid) warpBase += c;
        cnt += c;
    }

    if (keepIt) {
        int wpos = b * MAXN + s * SLICE + warpBase + myOff;
        g_c1[wpos] = p1;
        g_c2[wpos] = make_float4(col[g * 3 + 0], col[g * 3 + 1], col[g * 3 + 2], 0.f);
    }
    if (t == 0) g_cntS[b * MAXSLICES + s] = cnt;
}

// grid = B, 256 threads: scan the 32 slice counts, copy survivors densely.
__global__ void __launch_bounds__(NT)
pack_kernel(int numSlices) {
    __shared__ int sOff[MAXSLICES + 1];

    const int b = blockIdx.x;
    const int t = threadIdx.x;

    if (t < 32) {
        int c = (t < numSlices) ? g_cntS[b * MAXSLICES + t] : 0;
        int incl = c;
        #pragma unroll
        for (int o = 1; o < 32; o <<= 1) {
            int v = __shfl_up_sync(0xffffffffu, incl, o);
            if (t >= o) incl += v;
        }
        sOff[t + 1] = incl;
        if (t == 0) sOff[0] = 0;
        if (t == 31) g_M[b] = incl;
    }
    __syncthreads();

    const float4* __restrict__ C1 = g_c1 + b * MAXN;
    const float4* __restrict__ C2 = g_c2 + b * MAXN;
    float4* __restrict__ D1 = g_d1 + b * MAXN;
    float4* __restrict__ D2 = g_d2 + b * MAXN;

    for (int s = 0; s < numSlices; ++s) {
        int o0 = sOff[s];
        int cnt = sOff[s + 1] - o0;
        for (int i = t; i < cnt; i += NT) {
            D1[o0 + i] = C1[s * SLICE + i];
            D2[o0 + i] = C2[s * SLICE + i];
        }
    }
}

__global__ void __launch_bounds__(NT)
render_kernel(float* __restrict__ out) {
    __shared__ unsigned short sIdx[MAXN];   // tile survivors (dense-list positions)
    __shared__ int sWarp[NT / 32];

    const int t    = threadIdx.x;
    const int lane = t & 31;
    const int wid  = t >> 5;                // 0..7
    const int b    = blockIdx.z;
    const int x0   = blockIdx.x * TILE;
    const int y0   = blockIdx.y * TILE;
    const int px   = x0 + (t & (TILE - 1));
    const int py   = y0 + (t >> 4);
    const float xf = (float)px;
    const float yf = (float)py;

    const float fx0 = (float)x0, fx1 = (float)(x0 + TILE - 1);
    const float fy0 = (float)y0, fy1 = (float)(y0 + TILE - 1);

    const float4* __restrict__ D1 = g_d1 + b * MAXN;
    const float4* __restrict__ D2 = g_d2 + b * MAXN;
    const int M = g_M[b];

    // ---- Phase 1: tile-bbox test over the dense visible list ----
    unsigned keep = 0;
    int k = 0, j = 0;
    for (int i = t; i < M; i += NT, ++j) {
        float4 p = D1[i];
        float dx = fmaxf(0.f, fmaxf(fx0 - p.x, p.x - fx1));
        float dy = fmaxf(0.f, fmaxf(fy0 - p.y, p.y - fy1));
        float amax = fmaf(p.z, fmaf(dx, dx, dy * dy), p.w);
        if (amax > -60.f) { keep |= (1u << j); ++k; }
    }

    // ---- Phase 2: warp scan + 8-warp combine ----
    int incl = k;
    #pragma unroll
    for (int o = 1; o < 32; o <<= 1) {
        int v = __shfl_up_sync(0xffffffffu, incl, o);
        if (lane >= o) incl += v;
    }
    if (lane == 31) sWarp[wid] = incl;
    __syncthreads();

    int warpBase = 0, cnt = 0;
    #pragma unroll
    for (int w = 0; w < NT / 32; ++w) {
        int c = sWarp[w];
        if (w < wid) warpBase += c;
        cnt += c;
    }
    int wpos = warpBase + incl - k;

    // ---- Phase 3: deterministic compaction ----
    j = 0;
    for (int i = t; i < M; i += NT, ++j) {
        if (keep & (1u << j)) sIdx[wpos++] = (unsigned short)i;
    }
    __syncthreads();

    // ---- Phase 4: each pixel accumulates all tile survivors ----
    float accR = 0.f, accG = 0.f, accB = 0.f, accD = 0.f;
    #pragma unroll 2
    for (int i = 0; i < cnt; ++i) {
        int gi = (int)sIdx[i];
        float4 p1 = D1[gi];          // broadcast LDG.128, L1/L2-resident
        float4 p2 = D2[gi];
        float dx = xf - p1.x;
        float dy = yf - p1.y;
        float d2 = fmaf(dx, dx, dy * dy);
        float e  = exp2f(fmaf(p1.z, d2, p1.w));
        accD += e;
        accR = fmaf(e, p2.x, accR);
        accG = fmaf(e, p2.y, accG);
        accB = fmaf(e, p2.z, accB);
    }

    float invd = 1.0f / (accD + 1e-8f);
    int o = ((b * 3 + 0) * IMG_H + py) * IMG_W + px;
    out[o]                     = accR * invd;
    out[o + IMG_H * IMG_W]     = accG * invd;
    out[o + 2 * IMG_H * IMG_W] = accB * invd;
}

extern "C" void kernel_launch(void* const* d_in, const int* in_sizes, int n_in,
                              void* d_out, int out_size) {
    const float* positions = (const float*)d_in[0];  // (N,3)
    const float* colors    = (const float*)d_in[1];  // (N,3)
    const float* opacities = (const float*)d_in[2];  // (N,1)
    const float* scales    = (const float*)d_in[3];  // (N,1)
    const float* qvec      = (const float*)d_in[4];  // (B,4)
    const float* tvec      = (const float*)d_in[5];  // (B,3)

    int N = in_sizes[0] / 3;
    int B = in_sizes[4] / 4;
    if (N > MAXN || B > MAXB) return;  // capacity guard (problem is N=4096, B=2)

    int numSlices = (N + SLICE - 1) / SLICE;
    dim3 pgrid(numSlices, B);
    prep_kernel<<<pgrid, SLICE>>>(positions, colors, opacities, scales, qvec, tvec, N);
    pack_kernel<<<B, NT>>>(numSlices);

    dim3 grid(IMG_W / TILE, IMG_H / TILE, B);
    render_kernel<<<grid, NT>>>((float*)d_out);
}

// round 9
// speedup vs baseline: 1.1789x; 1.0526x over previous
#include <cuda_runtime.h>
#include <math.h>

// Problem constants (fixed by reference)
#define IMG_W 128
#define IMG_H 128
#define TILE  16              // 16x16 tiles -> 8*8*B = 128 blocks (single wave)
#define NT    256             // one thread per pixel
#define CHUNK 1024            // gaussians per block iteration (4 per thread)
#define IPC   (CHUNK / NT)    // 4

// Fully fused: per-block inline prep + cull + compact + accumulate.
// No global scratch, single launch.
__global__ void __launch_bounds__(NT)
fused_kernel(float* __restrict__ out,
             const float* __restrict__ pos,
             const float* __restrict__ col,
             const float* __restrict__ opa,
             const float* __restrict__ sca,
             const float* __restrict__ qv,
             const float* __restrict__ tv,
             int N) {
    __shared__ float4 sP1[CHUNK];   // {projx, projy, K2, log2(op)}
    __shared__ float4 sP2[CHUNK];   // {r, g, b, 0}
    __shared__ int    sWarp[NT / 32];

    const int t    = threadIdx.x;
    const int lane = t & 31;
    const int wid  = t >> 5;
    const int b    = blockIdx.z;
    const int x0   = blockIdx.x * TILE;
    const int y0   = blockIdx.y * TILE;
    const int px   = x0 + (t & (TILE - 1));
    const int py   = y0 + (t >> 4);
    const float xf = (float)px;
    const float yf = (float)py;

    const float fx0 = (float)x0, fx1 = (float)(x0 + TILE - 1);
    const float fy0 = (float)y0, fy1 = (float)(y0 + TILE - 1);

    // Camera for this batch (broadcast loads, every thread computes the same R).
    float qw = qv[b * 4 + 0], qx = qv[b * 4 + 1], qy = qv[b * 4 + 2], qz = qv[b * 4 + 3];
    float inv = rsqrtf(qw * qw + qx * qx + qy * qy + qz * qz);
    qw *= inv; qx *= inv; qy *= inv; qz *= inv;
    const float R00 = 1.f - 2.f * (qy * qy + qz * qz), R01 = 2.f * (qx * qy - qz * qw), R02 = 2.f * (qx * qz + qy * qw);
    const float R10 = 2.f * (qx * qy + qz * qw), R11 = 1.f - 2.f * (qx * qx + qz * qz), R12 = 2.f * (qy * qz - qx * qw);
    const float R20 = 2.f * (qx * qz - qy * qw), R21 = 2.f * (qy * qz + qx * qw), R22 = 1.f - 2.f * (qx * qx + qy * qy);
    const float tx = tv[b * 3 + 0], ty = tv[b * 3 + 1], tz = tv[b * 3 + 2];

    float accR = 0.f, accG = 0.f, accB = 0.f, accD = 0.f;

    for (int base = 0; base < N; base += CHUNK) {
        // ---- Phase 1: inline prep + conservative tile cull (4 gaussians/thread) ----
        // Conservative: opacities < 1 => log2(op) <= 0, so K2*d2 > -60 is a superset.
        float pjx[IPC], pjy[IPC], k2v[IPC];
        unsigned keep = 0;
        int k = 0;
        #pragma unroll
        for (int i = 0; i < IPC; ++i) {
            int g = base + i * NT + t;
            if (g < N) {
                float ppx = pos[g * 3 + 0], ppy = pos[g * 3 + 1], ppz = pos[g * 3 + 2];
                float cxm = R00 * ppx + R01 * ppy + R02 * ppz + tx;
                float cym = R10 * ppx + R11 * ppy + R12 * ppz + ty;
                float czm = R20 * ppx + R21 * ppy + R22 * ppz + tz;
                float iz  = __fdividef(1.0f, czm);
                float projx = fmaf(cxm * iz, 500.0f, 64.0f);
                float projy = fmaf(cym * iz, 500.0f, 64.0f);

                float sc  = sca[g];
                float K2  = __fdividef(-0.72134752044f, sc * sc);  // -1/(2 var ln2)

                float dx = fmaxf(0.f, fmaxf(fx0 - projx, projx - fx1));
                float dy = fmaxf(0.f, fmaxf(fy0 - projy, projy - fy1));
                float amax = K2 * fmaf(dx, dx, dy * dy);
                if (amax > -60.f) {       // NaN projections fail -> culled
                    keep |= (1u << i);
                    ++k;
                    pjx[i] = projx; pjy[i] = projy; k2v[i] = K2;
                }
            }
        }

        // ---- Phase 2: warp scan + 8-warp combine (deterministic order) ----
        int incl = k;
        #pragma unroll
        for (int o = 1; o < 32; o <<= 1) {
            int v = __shfl_up_sync(0xffffffffu, incl, o);
            if (lane >= o) incl += v;
        }
        if (lane == 31) sWarp[wid] = incl;
        __syncthreads();

        int warpBase = 0, cnt = 0;
        #pragma unroll
        for (int w = 0; w < NT / 32; ++w) {
            int c = sWarp[w];
            if (w < wid) warpBase += c;
            cnt += c;
        }
        int wpos = warpBase + incl - k;

        // ---- Phase 3: write survivors to shared (opacity/colors loaded here only) ----
        #pragma unroll
        for (int i = 0; i < IPC; ++i) {
            if (keep & (1u << i)) {
                int g = base + i * NT + t;
                float lo = log2f(fmaxf(opa[g], 1e-30f));
                sP1[wpos] = make_float4(pjx[i], pjy[i], k2v[i], lo);
                sP2[wpos] = make_float4(col[g * 3 + 0], col[g * 3 + 1], col[g * 3 + 2], 0.f);
                ++wpos;
            }
        }
        __syncthreads();

        // ---- Phase 4: accumulate survivors (broadcast LDS.128) ----
        #pragma unroll 2
        for (int i = 0; i < cnt; ++i) {
            float4 p1 = sP1[i];
            float4 p2 = sP2[i];
            float dx = xf - p1.x;
            float dy = yf - p1.y;
            float d2 = fmaf(dx, dx, dy * dy);
            float e  = exp2f(fmaf(p1.z, d2, p1.w));
            accD += e;
            accR = fmaf(e, p2.x, accR);
            accG = fmaf(e, p2.y, accG);
            accB = fmaf(e, p2.z, accB);
        }
        __syncthreads();   // protect shared reuse by next chunk
    }

    float invd = 1.0f / (accD + 1e-8f);
    int o = ((b * 3 + 0) * IMG_H + py) * IMG_W + px;
    out[o]                     = accR * invd;
    out[o + IMG_H * IMG_W]     = accG * invd;
    out[o + 2 * IMG_H * IMG_W] = accB * invd;
}

extern "C" void kernel_launch(void* const* d_in, const int* in_sizes, int n_in,
                              void* d_out, int out_size) {
    const float* positions = (const float*)d_in[0];  // (N,3)
    const float* colors    = (const float*)d_in[1];  // (N,3)
    const float* opacities = (const float*)d_in[2];  // (N,1)
    const float* scales    = (const float*)d_in[3];  // (N,1)
    const float* qvec      = (const float*)d_in[4];  // (B,4)
    const float* tvec      = (const float*)d_in[5];  // (B,3)

    int N = in_sizes[0] / 3;
    int B = in_sizes[4] / 4;

    dim3 grid(IMG_W / TILE, IMG_H / TILE, B);
    fused_kernel<<<grid, NT>>>((float*)d_out, positions, colors, opacities,
                               scales, qvec, tvec, N);
}

// round 10
// speedup vs baseline: 1.5395x; 1.3058x over previous
#include <cuda_runtime.h>
#include <math.h>

// Problem constants (fixed by reference)
#define IMG_W 128
#define IMG_H 128
#define TILE  16              // 16x16 tiles -> 8*8*B = 128 blocks (single wave)
#define PIX   256             // pixels per tile
#define SPLIT 4               // gaussian-axis interleave in accumulate
#define NT    1024            // threads per block
#define CHUNK 1024            // gaussians per chunk (1 per thread)
#define NWARP (NT / 32)       // 32

// Fully fused: inline prep + cull + compact + accumulate. One launch, no scratch.
__global__ void __launch_bounds__(NT)
fused_kernel(float* __restrict__ out,
             const float* __restrict__ pos,
             const float* __restrict__ col,
             const float* __restrict__ opa,
             const float* __restrict__ sca,
             const float* __restrict__ qv,
             const float* __restrict__ tv,
             int N) {
    __shared__ float4 sP1[CHUNK];     // {projx, projy, K2, log2(op)} ; reused as sAcc
    __shared__ float4 sP2[CHUNK];     // {r, g, b, 0}
    __shared__ int    sWCnt[NWARP];   // per-warp survivor counts
    __shared__ int    sWOff[NWARP];   // exclusive warp offsets
    __shared__ int    sTot;           // chunk survivor total

    const int t    = threadIdx.x;
    const int lane = t & 31;
    const int wid  = t >> 5;          // 0..31
    const int sub  = wid >> 3;        // 0..3 : accumulate slice
    const int pt   = t & (PIX - 1);   // pixel 0..255
    const int b    = blockIdx.z;
    const int x0   = blockIdx.x * TILE;
    const int y0   = blockIdx.y * TILE;
    const float xf = (float)(x0 + (pt & (TILE - 1)));
    const float yf = (float)(y0 + (pt >> 4));

    const float fx0 = (float)x0, fx1 = (float)(x0 + TILE - 1);
    const float fy0 = (float)y0, fy1 = (float)(y0 + TILE - 1);

    // Camera for this batch (broadcast loads; every thread computes the same R).
    float qw = qv[b * 4 + 0], qx = qv[b * 4 + 1], qy = qv[b * 4 + 2], qz = qv[b * 4 + 3];
    float inv = rsqrtf(qw * qw + qx * qx + qy * qy + qz * qz);
    qw *= inv; qx *= inv; qy *= inv; qz *= inv;
    const float R00 = 1.f - 2.f * (qy * qy + qz * qz), R01 = 2.f * (qx * qy - qz * qw), R02 = 2.f * (qx * qz + qy * qw);
    const float R10 = 2.f * (qx * qy + qz * qw), R11 = 1.f - 2.f * (qx * qx + qz * qz), R12 = 2.f * (qy * qz - qx * qw);
    const float R20 = 2.f * (qx * qz - qy * qw), R21 = 2.f * (qy * qz + qx * qw), R22 = 1.f - 2.f * (qx * qx + qy * qy);
    const float tx = tv[b * 3 + 0], ty = tv[b * 3 + 1], tz = tv[b * 3 + 2];

    float accR = 0.f, accG = 0.f, accB = 0.f, accD = 0.f;

    for (int base = 0; base < N; base += CHUNK) {
        const int g = base + t;

        // ---- Phase 1: inline prep + conservative tile cull (1 gaussian/thread) ----
        // Conservative: opacity < 1 => log2(op) <= 0, so K2*d2 > -60 is a superset.
        bool keepIt = false;
        float projx = 0.f, projy = 0.f, K2 = 0.f;
        if (g < N) {
            float ppx = pos[g * 3 + 0], ppy = pos[g * 3 + 1], ppz = pos[g * 3 + 2];
            float sc  = sca[g];
            float cxm = R00 * ppx + R01 * ppy + R02 * ppz + tx;
            float cym = R10 * ppx + R11 * ppy + R12 * ppz + ty;
            float czm = R20 * ppx + R21 * ppy + R22 * ppz + tz;
            float iz  = __fdividef(1.0f, czm);
            projx = fmaf(cxm * iz, 500.0f, 64.0f);
            projy = fmaf(cym * iz, 500.0f, 64.0f);
            K2    = __fdividef(-0.72134752044f, sc * sc);   // -1/(2 var ln2)

            float dx = fmaxf(0.f, fmaxf(fx0 - projx, projx - fx1));
            float dy = fmaxf(0.f, fmaxf(fy0 - projy, projy - fy1));
            float amax = K2 * fmaf(dx, dx, dy * dy);
            keepIt = (amax > -60.f);                        // NaN fails -> culled
        }

        // ---- Phase 2: ballot within warp; warp 0 scans the 32 counts ----
        unsigned m = __ballot_sync(0xffffffffu, keepIt);
        int myOff = __popc(m & ((1u << lane) - 1u));
        if (lane == 0) sWCnt[wid] = __popc(m);
        __syncthreads();

        if (wid == 0) {
            int c = sWCnt[lane];
            int incl = c;
            #pragma unroll
            for (int o = 1; o < 32; o <<= 1) {
                int v = __shfl_up_sync(0xffffffffu, incl, o);
                if (lane >= o) incl += v;
            }
            sWOff[lane] = incl - c;      // exclusive
            if (lane == 31) sTot = incl;
        }
        __syncthreads();

        // ---- Phase 3: survivors write params; opacity/colors loaded here only ----
        if (keepIt) {
            int wpos = sWOff[wid] + myOff;
            float lo = log2f(fmaxf(opa[g], 1e-30f));
            sP1[wpos] = make_float4(projx, projy, K2, lo);
            sP2[wpos] = make_float4(col[g * 3 + 0], col[g * 3 + 1], col[g * 3 + 2], 0.f);
        }
        __syncthreads();

        // ---- Phase 4: accumulate survivors, SPLIT-strided (broadcast LDS.128) ----
        const int cnt = sTot;
        #pragma unroll 2
        for (int i = sub; i < cnt; i += SPLIT) {
            float4 p1 = sP1[i];
            float4 p2 = sP2[i];
            float dx = xf - p1.x;
            float dy = yf - p1.y;
            float d2 = fmaf(dx, dx, dy * dy);
            float e  = exp2f(fmaf(p1.z, d2, p1.w));
            accD += e;
            accR = fmaf(e, p2.x, accR);
            accG = fmaf(e, p2.y, accG);
            accB = fmaf(e, p2.z, accB);
        }
        __syncthreads();   // protect shared reuse by next chunk
    }

    // ---- Final: fixed-order combine of the 4 sub partials (reuse sP1 as sAcc) ----
    float4* sAcc = sP1;
    sAcc[t] = make_float4(accR, accG, accB, accD);
    __syncthreads();

    if (t < PIX) {
        float4 a0 = sAcc[t];
        float4 a1 = sAcc[t + PIX];
        float4 a2 = sAcc[t + 2 * PIX];
        float4 a3 = sAcc[t + 3 * PIX];
        float r  = (a0.x + a1.x) + (a2.x + a3.x);
        float g  = (a0.y + a1.y) + (a2.y + a3.y);
        float bl = (a0.z + a1.z) + (a2.z + a3.z);
        float d  = (a0.w + a1.w) + (a2.w + a3.w);
        float invd = 1.0f / (d + 1e-8f);
        int px = x0 + (t & (TILE - 1));
        int py = y0 + (t >> 4);
        int o = ((b * 3 + 0) * IMG_H + py) * IMG_W + px;
        out[o]                     = r  * invd;
        out[o + IMG_H * IMG_W]     = g  * invd;
        out[o + 2 * IMG_H * IMG_W] = bl * invd;
    }
}

extern "C" void kernel_launch(void* const* d_in, const int* in_sizes, int n_in,
                              void* d_out, int out_size) {
    const float* positions = (const float*)d_in[0];  // (N,3)
    const float* colors    = (const float*)d_in[1];  // (N,3)
    const float* opacities = (const float*)d_in[2];  // (N,1)
    const float* scales    = (const float*)d_in[3];  // (N,1)
    const float* qvec      = (const float*)d_in[4];  // (B,4)
    const float* tvec      = (const float*)d_in[5];  // (B,3)

    int N = in_sizes[0] / 3;
    int B = in_sizes[4] / 4;

    dim3 grid(IMG_W / TILE, IMG_H / TILE, B);
    fused_kernel<<<grid, NT>>>((float*)d_out, positions, colors, opacities,
                               scales, qvec, tvec, N);
}

// round 11
// speedup vs baseline: 1.5775x; 1.0246x over previous
#include <cuda_runtime.h>
#include <math.h>

// Problem constants (fixed by reference)
#define IMG_W 128
#define IMG_H 128
#define TILE  16              // 16x16 tiles -> 8*8*B = 128 blocks (single wave)
#define PIX   256             // pixels per tile
#define SPLIT 4               // gaussian-axis interleave in accumulate
#define NT    1024            // threads per block
#define CHUNK 1024            // gaussians per chunk (1 per thread)
#define NWARP (NT / 32)       // 32

// Fully fused, software-pipelined: inline prep + cull + compact + accumulate.
__global__ void __launch_bounds__(NT)
fused_kernel(float* __restrict__ out,
             const float* __restrict__ pos,
             const float* __restrict__ col,
             const float* __restrict__ opa,
             const float* __restrict__ sca,
             const float* __restrict__ qv,
             const float* __restrict__ tv,
             int N) {
    __shared__ float4 sP1[CHUNK];     // {projx, projy, K2, log2(op)} ; reused as sAcc
    __shared__ float4 sP2[CHUNK];     // {r, g, b, 0}
    __shared__ int    sWCnt[NWARP];   // per-warp survivor counts

    const int t    = threadIdx.x;
    const int lane = t & 31;
    const int wid  = t >> 5;          // 0..31
    const int sub  = wid >> 3;        // 0..3 : accumulate slice
    const int pt   = t & (PIX - 1);   // pixel 0..255
    const int b    = blockIdx.z;
    const int x0   = blockIdx.x * TILE;
    const int y0   = blockIdx.y * TILE;
    const float xf = (float)(x0 + (pt & (TILE - 1)));
    const float yf = (float)(y0 + (pt >> 4));

    const float fx0 = (float)x0, fx1 = (float)(x0 + TILE - 1);
    const float fy0 = (float)y0, fy1 = (float)(y0 + TILE - 1);

    // Camera for this batch (broadcast loads; every thread computes the same R).
    float qw = qv[b * 4 + 0], qx = qv[b * 4 + 1], qy = qv[b * 4 + 2], qz = qv[b * 4 + 3];
    float inv = rsqrtf(qw * qw + qx * qx + qy * qy + qz * qz);
    qw *= inv; qx *= inv; qy *= inv; qz *= inv;
    const float R00 = 1.f - 2.f * (qy * qy + qz * qz), R01 = 2.f * (qx * qy - qz * qw), R02 = 2.f * (qx * qz + qy * qw);
    const float R10 = 2.f * (qx * qy + qz * qw), R11 = 1.f - 2.f * (qx * qx + qz * qz), R12 = 2.f * (qy * qz - qx * qw);
    const float R20 = 2.f * (qx * qz - qy * qw), R21 = 2.f * (qy * qz + qx * qw), R22 = 1.f - 2.f * (qx * qx + qy * qy);
    const float tx = tv[b * 3 + 0], ty = tv[b * 3 + 1], tz = tv[b * 3 + 2];

    float accR = 0.f, accG = 0.f, accB = 0.f, accD = 0.f;

    // ---- Prologue: load chunk 0 inputs (8 independent LDGs) ----
    float cPx = 0.f, cPy = 0.f, cPz = 0.f, cSc = 1.f, cOp = 1e-30f;
    float cCr = 0.f, cCg = 0.f, cCb = 0.f;
    {
        int g = t;
        if (g < N) {
            cPx = pos[g * 3 + 0]; cPy = pos[g * 3 + 1]; cPz = pos[g * 3 + 2];
            cSc = sca[g]; cOp = opa[g];
            cCr = col[g * 3 + 0]; cCg = col[g * 3 + 1]; cCb = col[g * 3 + 2];
        }
    }

    for (int base = 0; base < N; base += CHUNK) {
        const bool valid = (base + t) < N;

        // ---- Phase 1: project + cull from registers (tight bound incl. log2 op) ----
        float czm = R20 * cPx + R21 * cPy + R22 * cPz + tz;
        float iz  = __fdividef(1.0f, czm);
        float projx = fmaf((R00 * cPx + R01 * cPy + R02 * cPz + tx) * iz, 500.0f, 64.0f);
        float projy = fmaf((R10 * cPx + R11 * cPy + R12 * cPz + ty) * iz, 500.0f, 64.0f);
        float K2 = __fdividef(-0.72134752044f, cSc * cSc);   // -1/(2 var ln2)
        float lo = log2f(fmaxf(cOp, 1e-30f));

        float dx = fmaxf(0.f, fmaxf(fx0 - projx, projx - fx1));
        float dy = fmaxf(0.f, fmaxf(fy0 - projy, projy - fy1));
        float amax = fmaf(K2, fmaf(dx, dx, dy * dy), lo);
        bool keepIt = valid && (amax > -60.f);               // NaN fails -> culled
        float svCr = cCr, svCg = cCg, svCb = cCb;

        // ---- Prefetch next chunk (drains behind compaction + accumulate) ----
        {
            int g = base + CHUNK + t;
            if (g < N) {
                cPx = pos[g * 3 + 0]; cPy = pos[g * 3 + 1]; cPz = pos[g * 3 + 2];
                cSc = sca[g]; cOp = opa[g];
                cCr = col[g * 3 + 0]; cCg = col[g * 3 + 1]; cCb = col[g * 3 + 2];
            }
        }

        // ---- Phase 2: ballot; counts to shared; one barrier serves two purposes
        // (counts visible + previous chunk's sP reads finished) ----
        unsigned m = __ballot_sync(0xffffffffu, keepIt);
        int myOff = __popc(m & ((1u << lane) - 1u));
        if (lane == 0) sWCnt[wid] = __popc(m);
        __syncthreads();

        // ---- Phase 3: every warp scans the 32 counts redundantly (no extra sync) ----
        int cvec = sWCnt[lane];
        int incl = cvec;
        #pragma unroll
        for (int o = 1; o < 32; o <<= 1) {
            int v = __shfl_up_sync(0xffffffffu, incl, o);
            if (lane >= o) incl += v;
        }
        int warpBase = __shfl_sync(0xffffffffu, incl - cvec, wid);
        int cnt      = __shfl_sync(0xffffffffu, incl, 31);

        if (keepIt) {
            int wpos = warpBase + myOff;
            sP1[wpos] = make_float4(projx, projy, K2, lo);
            sP2[wpos] = make_float4(svCr, svCg, svCb, 0.f);
        }
        __syncthreads();

        // ---- Phase 4: accumulate survivors, SPLIT-strided (broadcast LDS.128) ----
        #pragma unroll 2
        for (int i = sub; i < cnt; i += SPLIT) {
            float4 p1 = sP1[i];
            float4 p2 = sP2[i];
            float ddx = xf - p1.x;
            float ddy = yf - p1.y;
            float d2 = fmaf(ddx, ddx, ddy * ddy);
            float e  = exp2f(fmaf(p1.z, d2, p1.w));
            accD += e;
            accR = fmaf(e, p2.x, accR);
            accG = fmaf(e, p2.y, accG);
            accB = fmaf(e, p2.z, accB);
        }
        // no trailing sync: next iteration's post-ballot barrier protects sP reuse
    }

    // ---- Final: fixed-order combine of the 4 sub partials (reuse sP1 as sAcc) ----
    __syncthreads();
    float4* sAcc = sP1;
    sAcc[t] = make_float4(accR, accG, accB, accD);
    __syncthreads();

    if (t < PIX) {
        float4 a0 = sAcc[t];
        float4 a1 = sAcc[t + PIX];
        float4 a2 = sAcc[t + 2 * PIX];
        float4 a3 = sAcc[t + 3 * PIX];
        float r  = (a0.x + a1.x) + (a2.x + a3.x);
        float g  = (a0.y + a1.y) + (a2.y + a3.y);
        float bl = (a0.z + a1.z) + (a2.z + a3.z);
        float d  = (a0.w + a1.w) + (a2.w + a3.w);
        float invd = 1.0f / (d + 1e-8f);
        int px = x0 + (t & (TILE - 1));
        int py = y0 + (t >> 4);
        int o = ((b * 3 + 0) * IMG_H + py) * IMG_W + px;
        out[o]                     = r  * invd;
        out[o + IMG_H * IMG_W]     = g  * invd;
        out[o + 2 * IMG_H * IMG_W] = bl * invd;
    }
}

extern "C" void kernel_launch(void* const* d_in, const int* in_sizes, int n_in,
                              void* d_out, int out_size) {
    const float* positions = (const float*)d_in[0];  // (N,3)
    const float* colors    = (const float*)d_in[1];  // (N,3)
    const float* opacities = (const float*)d_in[2];  // (N,1)
    const float* scales    = (const float*)d_in[3];  // (N,1)
    const float* qvec      = (const float*)d_in[4];  // (B,4)
    const float* tvec      = (const float*)d_in[5];  // (B,3)

    int N = in_sizes[0] / 3;
    int B = in_sizes[4] / 4;

    dim3 grid(IMG_W / TILE, IMG_H / TILE, B);
    fused_kernel<<<grid, NT>>>((float*)d_out, positions, colors, opacities,
                               scales, qvec, tvec, N);
}